// round 3
// baseline (speedup 1.0000x reference)
#include <cuda_runtime.h>
#include <cuda_bf16.h>
#include <math.h>

// Problem constants (fixed by the reference setup_inputs):
//   theta: float32 [4]    (degrees)
//   image: float32 [3, 80, 80]
//   out:   float32 [4, 3, 80, 80]
#define B_ 4
#define C_ 3
#define H_ 80
#define W_ 80
#define N_ (H_ * W_)

__global__ __launch_bounds__(128)
void rotation_bilinear_kernel(const float* __restrict__ theta,
                              const float* __restrict__ image,
                              float* __restrict__ out)
{
    int idx = blockIdx.x * blockDim.x + threadIdx.x;   // b * N + n
    if (idx >= B_ * N_) return;

    const int b = idx / N_;
    const int n = idx - b * N_;
    const int gy = n / W_;
    const int gx = n - gy * W_;

    const float cx = (W_ - 1) * 0.5f;
    const float cy = (H_ - 1) * 0.5f;

    // deg -> rad
    const float th = theta[b] * 0.017453292519943295f;
    float s, c;
    __sincosf(th, &s, &c);
    // Refine with precise sinf/cosf? __sincosf has ~2^-21 abs error — sufficient
    // for rel_err 1e-3. But use precise versions to be safe on the tolerance:
    s = sinf(th);
    c = cosf(th);

    const float xr = (float)gx - cx;
    const float yr = (float)gy - cy;

    // rotation [[c, s], [-s, c]] applied to (xr, yr), then re-centered
    const float sx =  c * xr + s * yr + cx;
    const float sy = -s * xr + c * yr + cy;

    // Tent weights: only floor(sx) and floor(sx)+1 have nonzero weight.
    const float fx0 = floorf(sx);
    const float fy0 = floorf(sy);
    const int x0 = (int)fx0;
    const int y0 = (int)fy0;
    const int x1 = x0 + 1;
    const int y1 = y0 + 1;

    const float ax = sx - fx0;           // weight of x1 tap
    const float ay = sy - fy0;           // weight of y1 tap
    float wx0 = 1.0f - ax;
    float wx1 = ax;
    float wy0 = 1.0f - ay;
    float wy1 = ay;

    // Zero-padding: taps outside [0, W-1] / [0, H-1] contribute nothing
    const bool vx0 = (x0 >= 0) & (x0 < W_);
    const bool vx1 = (x1 >= 0) & (x1 < W_);
    const bool vy0 = (y0 >= 0) & (y0 < H_);
    const bool vy1 = (y1 >= 0) & (y1 < H_);
    if (!vx0) wx0 = 0.0f;
    if (!vx1) wx1 = 0.0f;
    if (!vy0) wy0 = 0.0f;
    if (!vy1) wy1 = 0.0f;

    // Clamp indices so loads are always in-bounds (weight is 0 when clamped)
    const int cx0 = vx0 ? x0 : 0;
    const int cx1 = vx1 ? x1 : 0;
    const int cy0 = vy0 ? y0 : 0;
    const int cy1 = vy1 ? y1 : 0;

    const float w00 = wy0 * wx0;
    const float w01 = wy0 * wx1;
    const float w10 = wy1 * wx0;
    const float w11 = wy1 * wx1;

    const int o00 = cy0 * W_ + cx0;
    const int o01 = cy0 * W_ + cx1;
    const int o10 = cy1 * W_ + cx0;
    const int o11 = cy1 * W_ + cx1;

    #pragma unroll
    for (int ch = 0; ch < C_; ch++) {
        const float* img = image + ch * N_;
        float v = w00 * img[o00] + w01 * img[o01]
                + w10 * img[o10] + w11 * img[o11];
        out[(b * C_ + ch) * N_ + n] = v;
    }
}

extern "C" void kernel_launch(void* const* d_in, const int* in_sizes, int n_in,
                              void* d_out, int out_size)
{
    const float* theta = (const float*)d_in[0];
    const float* image = (const float*)d_in[1];
    float* out = (float*)d_out;

    const int total = B_ * N_;           // 25600 threads
    const int tpb = 128;
    const int blocks = (total + tpb - 1) / tpb;  // 200 blocks
    rotation_bilinear_kernel<<<blocks, tpb>>>(theta, image, out);
}

// round 5
// speedup vs baseline: 1.0863x; 1.0863x over previous
#include <cuda_runtime.h>
#include <cuda_bf16.h>
#include <math.h>

// Problem constants (fixed by the reference setup_inputs):
//   theta: float32 [4]    (degrees)
//   image: float32 [3, 80, 80]
//   out:   float32 [4, 3, 80, 80]
#define B_ 4
#define C_ 3
#define H_ 80
#define W_ 80
#define N_ (H_ * W_)

// Grid: (H_, B_) blocks of W_ threads. No integer division anywhere.
__global__ __launch_bounds__(W_)
void rotation_bilinear_kernel(const float* __restrict__ theta,
                              const float* __restrict__ image,
                              float* __restrict__ out)
{
    const int gx = threadIdx.x;      // 0..79
    const int gy = blockIdx.x;       // 0..79
    const int b  = blockIdx.y;       // 0..3

    const float cx = (W_ - 1) * 0.5f;
    const float cy = (H_ - 1) * 0.5f;

    // deg -> rad, fast hardware sincos (MUFU). |th| <~ 2.1 rad; abs err ~2^-21,
    // far inside the 1e-3 rel_err budget.
    const float th = __ldg(&theta[b]) * 0.017453292519943295f;
    float s, c;
    __sincosf(th, &s, &c);

    const float xr = (float)gx - cx;
    const float yr = (float)gy - cy;

    // rotation [[c, s], [-s, c]] applied to (xr, yr), then re-centered
    const float sx =  c * xr + s * yr + cx;
    const float sy = -s * xr + c * yr + cy;

    // Only floor(sx) / floor(sx)+1 taps have nonzero tent weight.
    const float fx0 = floorf(sx);
    const float fy0 = floorf(sy);
    const int x0 = (int)fx0;
    const int y0 = (int)fy0;
    const int x1 = x0 + 1;
    const int y1 = y0 + 1;

    const float ax = sx - fx0;
    const float ay = sy - fy0;
    float wx0 = 1.0f - ax;
    float wx1 = ax;
    float wy0 = 1.0f - ay;
    float wy1 = ay;

    // Zero padding outside the image
    const bool vx0 = (x0 >= 0) & (x0 < W_);
    const bool vx1 = (x1 >= 0) & (x1 < W_);
    const bool vy0 = (y0 >= 0) & (y0 < H_);
    const bool vy1 = (y1 >= 0) & (y1 < H_);
    if (!vx0) wx0 = 0.0f;
    if (!vx1) wx1 = 0.0f;
    if (!vy0) wy0 = 0.0f;
    if (!vy1) wy1 = 0.0f;

    // Clamp indices so loads are always in-bounds (weight 0 when clamped)
    const int cxi0 = vx0 ? x0 : 0;
    const int cxi1 = vx1 ? x1 : 0;
    const int cyi0 = vy0 ? y0 : 0;
    const int cyi1 = vy1 ? y1 : 0;

    const float w00 = wy0 * wx0;
    const float w01 = wy0 * wx1;
    const float w10 = wy1 * wx0;
    const float w11 = wy1 * wx1;

    const int o00 = cyi0 * W_ + cxi0;
    const int o01 = cyi0 * W_ + cxi1;
    const int o10 = cyi1 * W_ + cxi0;
    const int o11 = cyi1 * W_ + cxi1;

    const int n = gy * W_ + gx;

    #pragma unroll
    for (int ch = 0; ch < C_; ch++) {
        const float* img = image + ch * N_;
        float v = w00 * __ldg(img + o00) + w01 * __ldg(img + o01)
                + w10 * __ldg(img + o10) + w11 * __ldg(img + o11);
        out[(b * C_ + ch) * N_ + n] = v;
    }
}

extern "C" void kernel_launch(void* const* d_in, const int* in_sizes, int n_in,
                              void* d_out, int out_size)
{
    const float* theta = (const float*)d_in[0];
    const float* image = (const float*)d_in[1];
    float* out = (float*)d_out;

    dim3 grid(H_, B_);   // 80 x 4 = 320 blocks, all co-resident in one wave
    rotation_bilinear_kernel<<<grid, W_>>>(theta, image, out);
}